// round 8
// baseline (speedup 1.0000x reference)
#include <cuda_runtime.h>
#include <cstdint>
#include <math.h>

#define NE   8
#define DD   1024
#define FF   4096
#define TMAX 4096

// ---------------- device scratch ----------------
__device__ int   g_cnt[NE];
__device__ int   g_tok[NE * TMAX];
__device__ float g_wt [NE * TMAX];
__device__ float g_Xc [(size_t)TMAX * DD];          // tf32-rounded x
__device__ float g_w1c[(size_t)NE * DD * FF];       // tf32-rounded w1
__device__ float g_w3c[(size_t)NE * DD * FF];
__device__ float g_w2c[(size_t)NE * FF * DD];
__device__ float g_H  [(size_t)NE * TMAX * FF];     // SwiGLU acts (tf32-rounded)

// ---------------- helpers ----------------
__device__ __forceinline__ uint32_t smem_u32(const void* p) {
    uint32_t a;
    asm("{ .reg .u64 t; cvta.to.shared.u64 t, %1; cvt.u32.u64 %0, t; }" : "=r"(a) : "l"(p));
    return a;
}
__device__ __forceinline__ void cp16(uint32_t dst, const void* src) {
    asm volatile("cp.async.cg.shared.global [%0], [%1], 16;" :: "r"(dst), "l"(src));
}
__device__ __forceinline__ void cp_commit() { asm volatile("cp.async.commit_group;"); }
__device__ __forceinline__ void cp_wait2()  { asm volatile("cp.async.wait_group 2;"); }

__device__ __forceinline__ uint32_t to_tf32(float f) {
    uint32_t u;
    asm("cvt.rna.tf32.f32 %0, %1;" : "=r"(u) : "f"(f));
    return u;
}
__device__ __forceinline__ void mma8(float* c, const uint32_t* a, const uint32_t* b) {
    asm volatile(
        "mma.sync.aligned.m16n8k8.row.col.f32.tf32.tf32.f32 "
        "{%0,%1,%2,%3}, {%4,%5,%6,%7}, {%8,%9}, {%0,%1,%2,%3};"
        : "+f"(c[0]), "+f"(c[1]), "+f"(c[2]), "+f"(c[3])
        : "r"(a[0]), "r"(a[1]), "r"(a[2]), "r"(a[3]), "r"(b[0]), "r"(b[1]));
}

// ---------------- small kernels ----------------
__global__ void zero_cnt_kernel() { if (threadIdx.x < NE) g_cnt[threadIdx.x] = 0; }

// single conv for x (keeps launch count low)
__global__ void conv_x_kernel(const float4* __restrict__ s, float4* __restrict__ d, int n4) {
    int i = blockIdx.x * blockDim.x + threadIdx.x;
    int stride = gridDim.x * blockDim.x;
    for (; i < n4; i += stride) {
        float4 v = s[i];
        uint4 o;
        o.x = to_tf32(v.x); o.y = to_tf32(v.y); o.z = to_tf32(v.z); o.w = to_tf32(v.w);
        d[i] = *(float4*)&o;
    }
}

// merged conv for all three weights (one launch instead of three)
__global__ void conv_w_kernel(const float4* __restrict__ s1, float4* __restrict__ d1,
                              const float4* __restrict__ s2, float4* __restrict__ d2,
                              const float4* __restrict__ s3, float4* __restrict__ d3,
                              int n4) {
    int i = blockIdx.x * blockDim.x + threadIdx.x;
    int stride = gridDim.x * blockDim.x;
    for (; i < 3 * n4; i += stride) {
        int seg = i / n4, off = i - seg * n4;
        const float4* s = (seg == 0) ? s1 : (seg == 1) ? s2 : s3;
        float4*       d = (seg == 0) ? d1 : (seg == 1) ? d2 : d3;
        float4 v = s[off];
        uint4 o;
        o.x = to_tf32(v.x); o.y = to_tf32(v.y); o.z = to_tf32(v.z); o.w = to_tf32(v.w);
        d[off] = *(float4*)&o;
    }
}

__global__ void gate_kernel(const float* __restrict__ x,
                            const float* __restrict__ gw, int T) {
    int warp = (blockIdx.x * blockDim.x + threadIdx.x) >> 5;
    int lane = threadIdx.x & 31;
    if (warp >= T) return;
    const float* xr = x + (size_t)warp * DD;
    float acc[NE];
#pragma unroll
    for (int e = 0; e < NE; e++) acc[e] = 0.f;
    for (int d = lane; d < DD; d += 32) {
        float xv = xr[d];
        const float* g = gw + (size_t)d * NE;
#pragma unroll
        for (int e = 0; e < NE; e++) acc[e] += xv * g[e];
    }
#pragma unroll
    for (int e = 0; e < NE; e++)
#pragma unroll
        for (int off = 16; off > 0; off >>= 1)
            acc[e] += __shfl_xor_sync(0xffffffffu, acc[e], off);
    if (lane == 0) {
        int i0 = 0; float v0 = acc[0];
#pragma unroll
        for (int e = 1; e < NE; e++) if (acc[e] > v0) { v0 = acc[e]; i0 = e; }
        int i1 = -1; float v1 = -3.0e38f;
#pragma unroll
        for (int e = 0; e < NE; e++)
            if (e != i0 && acc[e] > v1) { v1 = acc[e]; i1 = e; }
        float t  = expf(v1 - v0);
        float w0 = 1.f / (1.f + t);
        float w1 = t / (1.f + t);
        int s0 = atomicAdd(&g_cnt[i0], 1);
        g_tok[i0 * TMAX + s0] = warp; g_wt[i0 * TMAX + s0] = w0;
        int s1 = atomicAdd(&g_cnt[i1], 1);
        g_tok[i1 * TMAX + s1] = warp; g_wt[i1 * TMAX + s1] = w1;
    }
}

// ======================= GEMM1: H = silu(X W1) * (X W3) * wgt =======================
// block 128x64, BK=32, 8 warps (4m x 2n), warp tile 32x32, dual accumulators.
// smem stage: A[128][36] (18432B) + B1[32][72] (9216B) + B3[32][72] -> 36864B.
// 3 stages = 110592B/CTA, 2 CTAs/SM (221KB <= 228KB): deep cp.async overlap
// AND cross-CTA latency hiding.
#define G1_STAGE_F 9216     // floats per stage
#define G1_SMEM   (3 * 36864)

__global__ void __launch_bounds__(256, 2)
gemm1_mma(const float* __restrict__ Xc,
          const float* __restrict__ w1c,
          const float* __restrict__ w3c) {
    const int e    = blockIdx.z;
    const int cnt  = g_cnt[e];
    const int row0 = blockIdx.x * 128;   // m-tile: FAST index
    if (row0 >= cnt) return;
    const int n0   = blockIdx.y * 64;    // n-tile: SLOW index

    extern __shared__ float sm[];
    const uint32_t sbase = smem_u32(sm);

    const int tid  = threadIdx.x;
    const int lane = tid & 31;
    const int wm   = (tid >> 5) & 3;     // warp m: 0..3  (32 rows each)
    const int wn   = (tid >> 5) >> 2;    // warp n: 0..1  (32 cols each)
    const int gId  = lane >> 2;          // 0..7
    const int tId  = lane & 3;           // 0..3

    // ---- cp.async source/dst precompute ----
    const float* asrc[4]; uint32_t adst[4];
#pragma unroll
    for (int j = 0; j < 4; j++) {
        int c = tid + 256 * j;
        int row = c >> 3, kc = c & 7;
        int rr = row0 + row; if (rr >= cnt) rr = cnt - 1;
        int tok = g_tok[e * TMAX + rr];
        asrc[j] = Xc + (size_t)tok * DD + kc * 4;
        adst[j] = 144u * row + 16u * kc;
    }
    const float* bsrc[4]; uint32_t bdst[4];
#pragma unroll
    for (int j = 0; j < 4; j++) {
        int c = tid + 256 * j;
        int mat = c >> 9, cc = c & 511;
        int row = cc >> 4, nc = cc & 15;
        const float* w = mat ? w3c : w1c;
        bsrc[j] = w + (size_t)e * DD * FF + (size_t)row * FF + n0 + nc * 4;
        bdst[j] = 18432u + (uint32_t)mat * 9216u + row * 288u + nc * 16u;
    }

#define G1_ISSUE(KT, S) do {                                        \
        uint32_t so_ = sbase + (uint32_t)(S) * 36864u;              \
        int k0_ = (KT) * 32;                                        \
        _Pragma("unroll")                                           \
        for (int j = 0; j < 4; j++) cp16(so_ + adst[j], asrc[j] + k0_); \
        _Pragma("unroll")                                           \
        for (int j = 0; j < 4; j++) cp16(so_ + bdst[j], bsrc[j] + (size_t)k0_ * FF); \
    } while (0)

    G1_ISSUE(0, 0); cp_commit();
    G1_ISSUE(1, 1); cp_commit();
    G1_ISSUE(2, 2); cp_commit();

    float acc1[2][4][4], acc3[2][4][4];
#pragma unroll
    for (int mi = 0; mi < 2; mi++)
#pragma unroll
        for (int ni = 0; ni < 4; ni++)
#pragma unroll
            for (int q = 0; q < 4; q++) { acc1[mi][ni][q] = 0.f; acc3[mi][ni][q] = 0.f; }

    const int NKT = DD / 32;   // 32
    for (int kt = 0; kt < NKT; kt++) {
        cp_wait2();
        __syncthreads();
        int st = kt % 3;
        const uint32_t* As = (const uint32_t*)(sm + st * G1_STAGE_F);
        const uint32_t* B1 = As + 4608;
        const uint32_t* B3 = As + 6912;

#pragma unroll
        for (int ks = 0; ks < 4; ks++) {
            const int kb = ks * 8;
            uint32_t a[2][4], b1[4][2], b3[4][2];
#pragma unroll
            for (int mi = 0; mi < 2; mi++) {
                int r = wm * 32 + mi * 16 + gId;
                int c = kb + tId;
                a[mi][0] = As[r * 36 + c];
                a[mi][1] = As[(r + 8) * 36 + c];
                a[mi][2] = As[r * 36 + c + 4];
                a[mi][3] = As[(r + 8) * 36 + c + 4];
            }
#pragma unroll
            for (int ni = 0; ni < 4; ni++) {
                int n = wn * 32 + ni * 8 + gId;
                int k = kb + tId;
                b1[ni][0] = B1[k * 72 + n];
                b1[ni][1] = B1[(k + 4) * 72 + n];
                b3[ni][0] = B3[k * 72 + n];
                b3[ni][1] = B3[(k + 4) * 72 + n];
            }
#pragma unroll
            for (int mi = 0; mi < 2; mi++)
#pragma unroll
                for (int ni = 0; ni < 4; ni++) {
                    mma8(acc1[mi][ni], a[mi], b1[ni]);
                    mma8(acc3[mi][ni], a[mi], b3[ni]);
                }
        }
        __syncthreads();
        if (kt + 3 < NKT) { G1_ISSUE(kt + 3, st); }
        cp_commit();
    }

    // ---- epilogue: SwiGLU * gate weight -> g_H (tf32-rounded) ----
#pragma unroll
    for (int mi = 0; mi < 2; mi++) {
        int rbase = row0 + wm * 32 + mi * 16 + gId;
#pragma unroll
        for (int half = 0; half < 2; half++) {
            int r = rbase + half * 8;
            if (r < cnt) {
                float wgt = g_wt[e * TMAX + r];
                float* hp = g_H + ((size_t)e * TMAX + r) * FF;
#pragma unroll
                for (int ni = 0; ni < 4; ni++) {
                    int col = n0 + wn * 32 + ni * 8 + tId * 2;
                    float h1a = acc1[mi][ni][half * 2 + 0];
                    float h1b = acc1[mi][ni][half * 2 + 1];
                    float h3a = acc3[mi][ni][half * 2 + 0];
                    float h3b = acc3[mi][ni][half * 2 + 1];
                    float oa = (h1a / (1.f + __expf(-h1a))) * h3a * wgt;
                    float ob = (h1b / (1.f + __expf(-h1b))) * h3b * wgt;
                    uint2 o;
                    o.x = to_tf32(oa); o.y = to_tf32(ob);
                    *(uint2*)(hp + col) = o;
                }
            }
        }
    }
}

// ======================= GEMM2: out[tok] += H W2 =======================
// block 128x128, BK=32, 8 warps (4m x 2n), warp tile 32x64.
// smem stage: A[128][36] (18432B) + B[32][136] (17408B) -> 35840B;
// 3 stages = 107520B/CTA, 2 CTAs/SM.
#define G2_STAGE_F 8960
#define G2_SMEM   (3 * 35840)

__global__ void __launch_bounds__(256, 2)
gemm2_mma(const float* __restrict__ w2c, float* __restrict__ out) {
    const int e    = blockIdx.z;
    const int cnt  = g_cnt[e];
    const int row0 = blockIdx.x * 128;   // m-tile: FAST index
    if (row0 >= cnt) return;
    const int n0   = blockIdx.y * 128;   // n-tile: SLOW index

    extern __shared__ float sm[];
    const uint32_t sbase = smem_u32(sm);

    const int tid  = threadIdx.x;
    const int lane = tid & 31;
    const int wm   = (tid >> 5) & 3;
    const int wn   = (tid >> 5) >> 2;
    const int gId  = lane >> 2;
    const int tId  = lane & 3;

    const float* asrc[4]; uint32_t adst[4];
#pragma unroll
    for (int j = 0; j < 4; j++) {
        int c = tid + 256 * j;
        int row = c >> 3, kc = c & 7;
        int rr = row0 + row; if (rr >= cnt) rr = cnt - 1;
        asrc[j] = g_H + ((size_t)e * TMAX + rr) * FF + kc * 4;
        adst[j] = 144u * row + 16u * kc;
    }
    const float* bsrc[4]; uint32_t bdst[4];
#pragma unroll
    for (int j = 0; j < 4; j++) {
        int c = tid + 256 * j;
        int row = c >> 5, nc = c & 31;
        bsrc[j] = w2c + (size_t)e * FF * DD + (size_t)row * DD + n0 + nc * 4;
        bdst[j] = 18432u + row * 544u + nc * 16u;
    }

#define G2_ISSUE(KT, S) do {                                        \
        uint32_t so_ = sbase + (uint32_t)(S) * 35840u;              \
        int k0_ = (KT) * 32;                                        \
        _Pragma("unroll")                                           \
        for (int j = 0; j < 4; j++) cp16(so_ + adst[j], asrc[j] + k0_); \
        _Pragma("unroll")                                           \
        for (int j = 0; j < 4; j++) cp16(so_ + bdst[j], bsrc[j] + (size_t)k0_ * DD); \
    } while (0)

    G2_ISSUE(0, 0); cp_commit();
    G2_ISSUE(1, 1); cp_commit();
    G2_ISSUE(2, 2); cp_commit();

    float acc[2][8][4];
#pragma unroll
    for (int mi = 0; mi < 2; mi++)
#pragma unroll
        for (int ni = 0; ni < 8; ni++)
#pragma unroll
            for (int q = 0; q < 4; q++) acc[mi][ni][q] = 0.f;

    const int NKT = FF / 32;   // 128
    for (int kt = 0; kt < NKT; kt++) {
        cp_wait2();
        __syncthreads();
        int st = kt % 3;
        const uint32_t* As = (const uint32_t*)(sm + st * G2_STAGE_F);
        const uint32_t* Bs = As + 4608;

#pragma unroll
        for (int ks = 0; ks < 4; ks++) {
            const int kb = ks * 8;
            uint32_t a[2][4], b[8][2];
#pragma unroll
            for (int mi = 0; mi < 2; mi++) {
                int r = wm * 32 + mi * 16 + gId;
                int c = kb + tId;
                a[mi][0] = As[r * 36 + c];
                a[mi][1] = As[(r + 8) * 36 + c];
                a[mi][2] = As[r * 36 + c + 4];
                a[mi][3] = As[(r + 8) * 36 + c + 4];
            }
#pragma unroll
            for (int ni = 0; ni < 8; ni++) {
                int n = wn * 64 + ni * 8 + gId;
                int k = kb + tId;
                b[ni][0] = Bs[k * 136 + n];
                b[ni][1] = Bs[(k + 4) * 136 + n];
            }
#pragma unroll
            for (int mi = 0; mi < 2; mi++)
#pragma unroll
                for (int ni = 0; ni < 8; ni++)
                    mma8(acc[mi][ni], a[mi], b[ni]);
        }
        __syncthreads();
        if (kt + 3 < NKT) { G2_ISSUE(kt + 3, st); }
        cp_commit();
    }

    // ---- epilogue: atomic scatter into out ----
#pragma unroll
    for (int mi = 0; mi < 2; mi++) {
        int rbase = row0 + wm * 32 + mi * 16 + gId;
#pragma unroll
        for (int half = 0; half < 2; half++) {
            int r = rbase + half * 8;
            if (r < cnt) {
                int tok = g_tok[e * TMAX + r];
                float* op = out + (size_t)tok * DD;
#pragma unroll
                for (int ni = 0; ni < 8; ni++) {
                    int col = n0 + wn * 64 + ni * 8 + tId * 2;
                    atomicAdd(&op[col],     acc[mi][ni][half * 2 + 0]);
                    atomicAdd(&op[col + 1], acc[mi][ni][half * 2 + 1]);
                }
            }
        }
    }
}

// ---------------- host ----------------
extern "C" void kernel_launch(void* const* d_in, const int* in_sizes, int n_in,
                              void* d_out, int out_size) {
    const float* x  = (const float*)d_in[0];
    const float* gw = (const float*)d_in[1];
    const float* w1 = (const float*)d_in[2];
    const float* w2 = (const float*)d_in[3];
    const float* w3 = (const float*)d_in[4];
    float* out = (float*)d_out;
    int T = in_sizes[0] / DD;   // 4096

    void *pXc, *pW1c, *pW2c, *pW3c;
    cudaGetSymbolAddress(&pXc,  g_Xc);
    cudaGetSymbolAddress(&pW1c, g_w1c);
    cudaGetSymbolAddress(&pW2c, g_w2c);
    cudaGetSymbolAddress(&pW3c, g_w3c);

    cudaFuncSetAttribute(gemm1_mma, cudaFuncAttributeMaxDynamicSharedMemorySize, G1_SMEM);
    cudaFuncSetAttribute(gemm2_mma, cudaFuncAttributeMaxDynamicSharedMemorySize, G2_SMEM);

    // Launch order chosen so ncu's fixed "-s 5 -c 1" lands on a GEMM kernel:
    // 0 memset, 1 zero_cnt, 2 gate, 3 conv_x, 4 conv_w, 5 gemm1, 6 gemm2
    cudaMemsetAsync(out, 0, (size_t)out_size * sizeof(float), 0);
    zero_cnt_kernel<<<1, 32>>>();
    gate_kernel<<<(T * 32 + 255) / 256, 256>>>(x, gw, T);

    int n4x = T * DD / 4;
    int n4w = NE * DD * FF / 4;
    conv_x_kernel<<<2048, 256>>>((const float4*)x, (float4*)pXc, n4x);
    conv_w_kernel<<<8192, 256>>>((const float4*)w1, (float4*)pW1c,
                                 (const float4*)w3, (float4*)pW3c,
                                 (const float4*)w2, (float4*)pW2c, n4w);

    dim3 g1(TMAX / 128, FF / 64, NE);
    gemm1_mma<<<g1, 256, G1_SMEM>>>((const float*)pXc, (const float*)pW1c, (const float*)pW3c);

    dim3 g2(TMAX / 128, DD / 128, NE);
    gemm2_mma<<<g2, 256, G2_SMEM>>>((const float*)pW2c, out);
}

// round 9
// speedup vs baseline: 1.6951x; 1.6951x over previous
#include <cuda_runtime.h>
#include <cuda_fp16.h>
#include <cstdint>
#include <math.h>

#define NE   8
#define DD   1024
#define FF   4096
#define TMAX 4096

// ---------------- device scratch ----------------
__device__ int    g_cnt[NE];
__device__ int    g_tok[NE * TMAX];
__device__ float  g_wt [NE * TMAX];
__device__ __half g_Xh [(size_t)TMAX * DD];          // fp16 x (k-major)
__device__ __half g_w1t[(size_t)NE * DD * FF];       // fp16 w1^T : [E][F][D] (n-major)
__device__ __half g_w3t[(size_t)NE * DD * FF];       // fp16 w3^T : [E][F][D]
__device__ __half g_w2t[(size_t)NE * FF * DD];       // fp16 w2^T : [E][D][F]
__device__ __half g_H  [(size_t)NE * TMAX * FF];     // fp16 SwiGLU acts (k-major)

// ---------------- helpers ----------------
__device__ __forceinline__ uint32_t smem_u32(const void* p) {
    uint32_t a;
    asm("{ .reg .u64 t; cvta.to.shared.u64 t, %1; cvt.u32.u64 %0, t; }" : "=r"(a) : "l"(p));
    return a;
}
__device__ __forceinline__ void cp16(uint32_t dst, const void* src) {
    asm volatile("cp.async.cg.shared.global [%0], [%1], 16;" :: "r"(dst), "l"(src));
}
__device__ __forceinline__ void cp_commit() { asm volatile("cp.async.commit_group;"); }
__device__ __forceinline__ void cp_wait1()  { asm volatile("cp.async.wait_group 1;"); }

// fp16 mma, k=16, fp32 accumulate
__device__ __forceinline__ void mma16(float* c, uint32_t a0, uint32_t a1, uint32_t a2,
                                      uint32_t a3, uint32_t b0, uint32_t b1) {
    asm volatile(
        "mma.sync.aligned.m16n8k16.row.col.f32.f16.f16.f32 "
        "{%0,%1,%2,%3}, {%4,%5,%6,%7}, {%8,%9}, {%0,%1,%2,%3};"
        : "+f"(c[0]), "+f"(c[1]), "+f"(c[2]), "+f"(c[3])
        : "r"(a0), "r"(a1), "r"(a2), "r"(a3), "r"(b0), "r"(b1));
}
__device__ __forceinline__ uint32_t pack_h2(float lo, float hi) {
    __half2 h = __floats2half2_rn(lo, hi);
    return *(uint32_t*)&h;
}

// ---------------- small kernels ----------------
__global__ void zero_cnt_kernel() { if (threadIdx.x < NE) g_cnt[threadIdx.x] = 0; }

__global__ void gate_kernel(const float* __restrict__ x,
                            const float* __restrict__ gw, int T) {
    int warp = (blockIdx.x * blockDim.x + threadIdx.x) >> 5;
    int lane = threadIdx.x & 31;
    if (warp >= T) return;
    const float* xr = x + (size_t)warp * DD;
    float acc[NE];
#pragma unroll
    for (int e = 0; e < NE; e++) acc[e] = 0.f;
    for (int d = lane; d < DD; d += 32) {
        float xv = xr[d];
        const float* g = gw + (size_t)d * NE;
#pragma unroll
        for (int e = 0; e < NE; e++) acc[e] += xv * g[e];
    }
#pragma unroll
    for (int e = 0; e < NE; e++)
#pragma unroll
        for (int off = 16; off > 0; off >>= 1)
            acc[e] += __shfl_xor_sync(0xffffffffu, acc[e], off);
    if (lane == 0) {
        int i0 = 0; float v0 = acc[0];
#pragma unroll
        for (int e = 1; e < NE; e++) if (acc[e] > v0) { v0 = acc[e]; i0 = e; }
        int i1 = -1; float v1 = -3.0e38f;
#pragma unroll
        for (int e = 0; e < NE; e++)
            if (e != i0 && acc[e] > v1) { v1 = acc[e]; i1 = e; }
        float t  = expf(v1 - v0);
        float w0 = 1.f / (1.f + t);
        float w1 = t / (1.f + t);
        int s0 = atomicAdd(&g_cnt[i0], 1);
        g_tok[i0 * TMAX + s0] = warp; g_wt[i0 * TMAX + s0] = w0;
        int s1 = atomicAdd(&g_cnt[i1], 1);
        g_tok[i1 * TMAX + s1] = warp; g_wt[i1 * TMAX + s1] = w1;
    }
}

// x -> fp16, elementwise
__global__ void conv_x_kernel(const float4* __restrict__ s, uint2* __restrict__ d, int n4) {
    int i = blockIdx.x * blockDim.x + threadIdx.x;
    int stride = gridDim.x * blockDim.x;
    for (; i < n4; i += stride) {
        float4 v = s[i];
        uint2 o;
        o.x = pack_h2(v.x, v.y);
        o.y = pack_h2(v.z, v.w);
        d[i] = o;
    }
}

// merged transpose + fp16 for all 3 weights:
// w1,w3: [NE][DD][FF] -> [NE][FF][DD];  w2: [NE][FF][DD] -> [NE][DD][FF]
#define TILES_W1 ((FF / 32) * (DD / 32) * NE)   // 32768
__global__ void trans_all_kernel(const float* __restrict__ w1, __half* __restrict__ d1,
                                 const float* __restrict__ w3, __half* __restrict__ d3,
                                 const float* __restrict__ w2, __half* __restrict__ d2) {
    __shared__ float t[32][33];
    int bid = blockIdx.x;
    const float* src; __half* dst; int R, C;
    if (bid < TILES_W1)          { src = w1; dst = d1; R = DD; C = FF; }
    else if (bid < 2 * TILES_W1) { src = w3; dst = d3; R = DD; C = FF; bid -= TILES_W1; }
    else                         { src = w2; dst = d2; R = FF; C = DD; bid -= 2 * TILES_W1; }
    int tilesC = C / 32, tilesR = R / 32;
    int b   = bid / (tilesC * tilesR);
    int rem = bid % (tilesC * tilesR);
    int c0 = (rem % tilesC) * 32, r0 = (rem / tilesC) * 32;
    const float* s = src + (size_t)b * R * C;
    __half* d = dst + (size_t)b * R * C;
    int tx = threadIdx.x & 31, ty = threadIdx.x >> 5;
#pragma unroll
    for (int i = 0; i < 32; i += 8)
        t[ty + i][tx] = s[(size_t)(r0 + ty + i) * C + c0 + tx];
    __syncthreads();
#pragma unroll
    for (int i = 0; i < 32; i += 8)
        d[(size_t)(c0 + ty + i) * R + r0 + tx] = __float2half_rn(t[tx][ty + i]);
}

// ======================= GEMM1: H = silu(X W1) * (X W3) * wgt =======================
// fp16 operands, BK=64, block 128x64, 8 warps (4m x 2n), warp tile 32x32 dual.
// A smem [128][72] halves (18432B); B1/B3 [64][72] halves (9216B each).
// Stage 36864B, 2 stages = 72KB -> 2 CTAs/SM. Bank-conflict-free (stride 144B).
#define G_STAGE_B 36864
#define G_SMEM   (2 * G_STAGE_B)

__global__ void __launch_bounds__(256, 2)
gemm1_mma(const __half* __restrict__ Xh,
          const __half* __restrict__ w1t,
          const __half* __restrict__ w3t) {
    const int e    = blockIdx.z;
    const int cnt  = g_cnt[e];
    const int row0 = blockIdx.x * 128;   // m fast
    if (row0 >= cnt) return;
    const int n0   = blockIdx.y * 64;

    extern __shared__ char smc[];
    const uint32_t sbase = smem_u32(smc);

    const int tid  = threadIdx.x;
    const int lane = tid & 31;
    const int wm   = (tid >> 5) & 3;
    const int wn   = (tid >> 5) >> 2;
    const int gId  = lane >> 2;
    const int tId  = lane & 3;

    // A: 128 rows x 64 halves = 128B/row -> 1024 x 16B chunks
    const __half* asrc[4]; uint32_t adst[4];
#pragma unroll
    for (int j = 0; j < 4; j++) {
        int c = tid + 256 * j;
        int row = c >> 3, kc = c & 7;
        int rr = row0 + row; if (rr >= cnt) rr = cnt - 1;
        int tok = g_tok[e * TMAX + rr];
        asrc[j] = Xh + (size_t)tok * DD + kc * 8;
        adst[j] = 144u * row + 16u * kc;
    }
    // B: 2 mats x 64 n x 8 chunks = 1024
    const __half* bsrc[4]; uint32_t bdst[4];
#pragma unroll
    for (int j = 0; j < 4; j++) {
        int c = tid + 256 * j;
        int mat = c >> 9, cc = c & 511;
        int n = cc >> 3, kc = cc & 7;
        const __half* w = mat ? w3t : w1t;
        bsrc[j] = w + (size_t)e * DD * FF + (size_t)(n0 + n) * DD + kc * 8;
        bdst[j] = 18432u + (uint32_t)mat * 9216u + 144u * n + 16u * kc;
    }

#define G1_ISSUE(KT, S) do {                                        \
        uint32_t so_ = sbase + (uint32_t)(S) * G_STAGE_B;           \
        int k0_ = (KT) * 64;                                        \
        _Pragma("unroll")                                           \
        for (int j = 0; j < 4; j++) cp16(so_ + adst[j], asrc[j] + k0_); \
        _Pragma("unroll")                                           \
        for (int j = 0; j < 4; j++) cp16(so_ + bdst[j], bsrc[j] + k0_); \
    } while (0)

    G1_ISSUE(0, 0); cp_commit();
    G1_ISSUE(1, 1); cp_commit();

    float acc1[2][4][4], acc3[2][4][4];
#pragma unroll
    for (int mi = 0; mi < 2; mi++)
#pragma unroll
        for (int ni = 0; ni < 4; ni++)
#pragma unroll
            for (int q = 0; q < 4; q++) { acc1[mi][ni][q] = 0.f; acc3[mi][ni][q] = 0.f; }

    const int NKT = DD / 64;   // 16
    for (int kt = 0; kt < NKT; kt++) {
        cp_wait1();
        __syncthreads();
        const __half* As = (const __half*)(smc + (kt & 1) * G_STAGE_B);
        const __half* B1 = As + 9216;
        const __half* B3 = As + 13824;

#pragma unroll
        for (int s = 0; s < 4; s++) {        // 4 x k16 steps
            const int k0 = 16 * s + 2 * tId;
            uint32_t a0[2], a1[2], a2[2], a3[2];
#pragma unroll
            for (int mi = 0; mi < 2; mi++) {
                int r = wm * 32 + mi * 16 + gId;
                a0[mi] = *(const uint32_t*)(As + r * 72 + k0);
                a1[mi] = *(const uint32_t*)(As + (r + 8) * 72 + k0);
                a2[mi] = *(const uint32_t*)(As + r * 72 + k0 + 8);
                a3[mi] = *(const uint32_t*)(As + (r + 8) * 72 + k0 + 8);
            }
#pragma unroll
            for (int ni = 0; ni < 4; ni++) {
                int n = wn * 32 + ni * 8 + gId;
                uint32_t b10 = *(const uint32_t*)(B1 + n * 72 + k0);
                uint32_t b11 = *(const uint32_t*)(B1 + n * 72 + k0 + 8);
                uint32_t b30 = *(const uint32_t*)(B3 + n * 72 + k0);
                uint32_t b31 = *(const uint32_t*)(B3 + n * 72 + k0 + 8);
#pragma unroll
                for (int mi = 0; mi < 2; mi++) {
                    mma16(acc1[mi][ni], a0[mi], a1[mi], a2[mi], a3[mi], b10, b11);
                    mma16(acc3[mi][ni], a0[mi], a1[mi], a2[mi], a3[mi], b30, b31);
                }
            }
        }
        __syncthreads();
        if (kt + 2 < NKT) { G1_ISSUE(kt + 2, kt & 1); }
        cp_commit();
    }

    // ---- epilogue: SwiGLU * gate weight -> g_H (fp16) ----
#pragma unroll
    for (int mi = 0; mi < 2; mi++) {
        int rbase = row0 + wm * 32 + mi * 16 + gId;
#pragma unroll
        for (int half = 0; half < 2; half++) {
            int r = rbase + half * 8;
            if (r < cnt) {
                float wgt = g_wt[e * TMAX + r];
                __half* hp = g_H + ((size_t)e * TMAX + r) * FF;
#pragma unroll
                for (int ni = 0; ni < 4; ni++) {
                    int col = n0 + wn * 32 + ni * 8 + tId * 2;
                    float h1a = acc1[mi][ni][half * 2 + 0];
                    float h1b = acc1[mi][ni][half * 2 + 1];
                    float h3a = acc3[mi][ni][half * 2 + 0];
                    float h3b = acc3[mi][ni][half * 2 + 1];
                    float oa = (h1a / (1.f + __expf(-h1a))) * h3a * wgt;
                    float ob = (h1b / (1.f + __expf(-h1b))) * h3b * wgt;
                    *(uint32_t*)(hp + col) = pack_h2(oa, ob);
                }
            }
        }
    }
}

// ======================= GEMM2: out[tok] += H W2 =======================
// fp16, BK=64, block 128x128, warp tile 32x64.
// A smem [128][72] halves; B [128][72] halves; stage 36864B, 2 stages.
__global__ void __launch_bounds__(256, 2)
gemm2_mma(const __half* __restrict__ w2t, float* __restrict__ out) {
    const int e    = blockIdx.z;
    const int cnt  = g_cnt[e];
    const int row0 = blockIdx.x * 128;
    if (row0 >= cnt) return;
    const int n0   = blockIdx.y * 128;

    extern __shared__ char smc[];
    const uint32_t sbase = smem_u32(smc);

    const int tid  = threadIdx.x;
    const int lane = tid & 31;
    const int wm   = (tid >> 5) & 3;
    const int wn   = (tid >> 5) >> 2;
    const int gId  = lane >> 2;
    const int tId  = lane & 3;

    const __half* asrc[4]; uint32_t adst[4];
#pragma unroll
    for (int j = 0; j < 4; j++) {
        int c = tid + 256 * j;
        int row = c >> 3, kc = c & 7;
        int rr = row0 + row; if (rr >= cnt) rr = cnt - 1;
        asrc[j] = g_H + ((size_t)e * TMAX + rr) * FF + kc * 8;
        adst[j] = 144u * row + 16u * kc;
    }
    const __half* bsrc[4]; uint32_t bdst[4];
#pragma unroll
    for (int j = 0; j < 4; j++) {
        int c = tid + 256 * j;
        int n = c >> 3, kc = c & 7;
        bsrc[j] = w2t + (size_t)e * FF * DD + (size_t)(n0 + n) * FF + kc * 8;
        bdst[j] = 18432u + 144u * n + 16u * kc;
    }

#define G2_ISSUE(KT, S) do {                                        \
        uint32_t so_ = sbase + (uint32_t)(S) * G_STAGE_B;           \
        int k0_ = (KT) * 64;                                        \
        _Pragma("unroll")                                           \
        for (int j = 0; j < 4; j++) cp16(so_ + adst[j], asrc[j] + k0_); \
        _Pragma("unroll")                                           \
        for (int j = 0; j < 4; j++) cp16(so_ + bdst[j], bsrc[j] + k0_); \
    } while (0)

    G2_ISSUE(0, 0); cp_commit();
    G2_ISSUE(1, 1); cp_commit();

    float acc[2][8][4];
#pragma unroll
    for (int mi = 0; mi < 2; mi++)
#pragma unroll
        for (int ni = 0; ni < 8; ni++)
#pragma unroll
            for (int q = 0; q < 4; q++) acc[mi][ni][q] = 0.f;

    const int NKT = FF / 64;   // 64
    for (int kt = 0; kt < NKT; kt++) {
        cp_wait1();
        __syncthreads();
        const __half* As = (const __half*)(smc + (kt & 1) * G_STAGE_B);
        const __half* Bs = As + 9216;

#pragma unroll
        for (int s = 0; s < 4; s++) {
            const int k0 = 16 * s + 2 * tId;
            uint32_t a0[2], a1[2], a2[2], a3[2];
#pragma unroll
            for (int mi = 0; mi < 2; mi++) {
                int r = wm * 32 + mi * 16 + gId;
                a0[mi] = *(const uint32_t*)(As + r * 72 + k0);
                a1[mi] = *(const uint32_t*)(As + (r + 8) * 72 + k0);
                a2[mi] = *(const uint32_t*)(As + r * 72 + k0 + 8);
                a3[mi] = *(const uint32_t*)(As + (r + 8) * 72 + k0 + 8);
            }
#pragma unroll
            for (int ni = 0; ni < 8; ni++) {
                int n = wn * 64 + ni * 8 + gId;
                uint32_t b0 = *(const uint32_t*)(Bs + n * 72 + k0);
                uint32_t b1 = *(const uint32_t*)(Bs + n * 72 + k0 + 8);
#pragma unroll
                for (int mi = 0; mi < 2; mi++)
                    mma16(acc[mi][ni], a0[mi], a1[mi], a2[mi], a3[mi], b0, b1);
            }
        }
        __syncthreads();
        if (kt + 2 < NKT) { G2_ISSUE(kt + 2, kt & 1); }
        cp_commit();
    }

    // ---- epilogue: atomic scatter into out (fp32) ----
#pragma unroll
    for (int mi = 0; mi < 2; mi++) {
        int rbase = row0 + wm * 32 + mi * 16 + gId;
#pragma unroll
        for (int half = 0; half < 2; half++) {
            int r = rbase + half * 8;
            if (r < cnt) {
                int tok = g_tok[e * TMAX + r];
                float* op = out + (size_t)tok * DD;
#pragma unroll
                for (int ni = 0; ni < 8; ni++) {
                    int col = n0 + wn * 64 + ni * 8 + tId * 2;
                    atomicAdd(&op[col],     acc[mi][ni][half * 2 + 0]);
                    atomicAdd(&op[col + 1], acc[mi][ni][half * 2 + 1]);
                }
            }
        }
    }
}

// ---------------- host ----------------
extern "C" void kernel_launch(void* const* d_in, const int* in_sizes, int n_in,
                              void* d_out, int out_size) {
    const float* x  = (const float*)d_in[0];
    const float* gw = (const float*)d_in[1];
    const float* w1 = (const float*)d_in[2];
    const float* w2 = (const float*)d_in[3];
    const float* w3 = (const float*)d_in[4];
    float* out = (float*)d_out;
    int T = in_sizes[0] / DD;   // 4096

    void *pXh, *pW1t, *pW2t, *pW3t;
    cudaGetSymbolAddress(&pXh,  g_Xh);
    cudaGetSymbolAddress(&pW1t, g_w1t);
    cudaGetSymbolAddress(&pW2t, g_w2t);
    cudaGetSymbolAddress(&pW3t, g_w3t);

    cudaFuncSetAttribute(gemm1_mma, cudaFuncAttributeMaxDynamicSharedMemorySize, G_SMEM);
    cudaFuncSetAttribute(gemm2_mma, cudaFuncAttributeMaxDynamicSharedMemorySize, G_SMEM);

    // Launch order keeps a GEMM at profile slot 5 whether or not memset counts:
    // [memset] zero gate conv_x trans_all gemm1 gemm2
    cudaMemsetAsync(out, 0, (size_t)out_size * sizeof(float), 0);
    zero_cnt_kernel<<<1, 32>>>();
    gate_kernel<<<(T * 32 + 255) / 256, 256>>>(x, gw, T);

    conv_x_kernel<<<2048, 256>>>((const float4*)x, (uint2*)pXh, T * DD / 4);
    trans_all_kernel<<<3 * TILES_W1, 256>>>(w1, (__half*)pW1t,
                                            w3, (__half*)pW3t,
                                            w2, (__half*)pW2t);

    dim3 g1(TMAX / 128, FF / 64, NE);
    gemm1_mma<<<g1, 256, G_SMEM>>>((const __half*)pXh, (const __half*)pW1t, (const __half*)pW3t);

    dim3 g2(TMAX / 128, DD / 128, NE);
    gemm2_mma<<<g2, 256, G_SMEM>>>((const __half*)pW2t, out);
}

// round 10
// speedup vs baseline: 1.8805x; 1.1094x over previous
#include <cuda_runtime.h>
#include <cuda_fp16.h>
#include <cstdint>
#include <math.h>

#define NE   8
#define DD   1024
#define FF   4096
#define TMAX 4096

// ---------------- device scratch ----------------
__device__ int    g_cnt[NE];
__device__ int    g_tok[NE * TMAX];
__device__ float  g_wt [NE * TMAX];
__device__ __half g_Xh [(size_t)TMAX * DD];          // fp16 x (k-major)
__device__ __half g_w1t[(size_t)NE * DD * FF];       // fp16 w1^T : [E][F][D] (n-major)
__device__ __half g_w3t[(size_t)NE * DD * FF];       // fp16 w3^T : [E][F][D]
__device__ __half g_w2t[(size_t)NE * FF * DD];       // fp16 w2^T : [E][D][F]
__device__ __half g_H  [(size_t)NE * TMAX * FF];     // fp16 SwiGLU acts (k-major)

// ---------------- helpers ----------------
__device__ __forceinline__ uint32_t smem_u32(const void* p) {
    uint32_t a;
    asm("{ .reg .u64 t; cvta.to.shared.u64 t, %1; cvt.u32.u64 %0, t; }" : "=r"(a) : "l"(p));
    return a;
}
__device__ __forceinline__ void cp16(uint32_t dst, const void* src) {
    asm volatile("cp.async.cg.shared.global [%0], [%1], 16;" :: "r"(dst), "l"(src));
}
__device__ __forceinline__ void cp_commit() { asm volatile("cp.async.commit_group;"); }
__device__ __forceinline__ void cp_wait1()  { asm volatile("cp.async.wait_group 1;"); }

// fp16 mma, k=16, fp32 accumulate
__device__ __forceinline__ void mma16(float* c, uint32_t a0, uint32_t a1, uint32_t a2,
                                      uint32_t a3, uint32_t b0, uint32_t b1) {
    asm volatile(
        "mma.sync.aligned.m16n8k16.row.col.f32.f16.f16.f32 "
        "{%0,%1,%2,%3}, {%4,%5,%6,%7}, {%8,%9}, {%0,%1,%2,%3};"
        : "+f"(c[0]), "+f"(c[1]), "+f"(c[2]), "+f"(c[3])
        : "r"(a0), "r"(a1), "r"(a2), "r"(a3), "r"(b0), "r"(b1));
}
// ldmatrix x4: one instruction loads 4 regs (4 8x8 b16 tiles)
__device__ __forceinline__ void ldsm4(uint32_t* r, uint32_t addr) {
    asm volatile("ldmatrix.sync.aligned.m8n8.x4.shared.b16 {%0,%1,%2,%3}, [%4];"
                 : "=r"(r[0]), "=r"(r[1]), "=r"(r[2]), "=r"(r[3]) : "r"(addr));
}
__device__ __forceinline__ uint32_t pack_h2(float lo, float hi) {
    __half2 h = __floats2half2_rn(lo, hi);
    return *(uint32_t*)&h;
}

// ---------------- small kernels ----------------
__global__ void zero_cnt_kernel() { if (threadIdx.x < NE) g_cnt[threadIdx.x] = 0; }

__global__ void gate_kernel(const float* __restrict__ x,
                            const float* __restrict__ gw, int T) {
    int warp = (blockIdx.x * blockDim.x + threadIdx.x) >> 5;
    int lane = threadIdx.x & 31;
    if (warp >= T) return;
    const float* xr = x + (size_t)warp * DD;
    float acc[NE];
#pragma unroll
    for (int e = 0; e < NE; e++) acc[e] = 0.f;
    for (int d = lane; d < DD; d += 32) {
        float xv = xr[d];
        const float* g = gw + (size_t)d * NE;
#pragma unroll
        for (int e = 0; e < NE; e++) acc[e] += xv * g[e];
    }
#pragma unroll
    for (int e = 0; e < NE; e++)
#pragma unroll
        for (int off = 16; off > 0; off >>= 1)
            acc[e] += __shfl_xor_sync(0xffffffffu, acc[e], off);
    if (lane == 0) {
        int i0 = 0; float v0 = acc[0];
#pragma unroll
        for (int e = 1; e < NE; e++) if (acc[e] > v0) { v0 = acc[e]; i0 = e; }
        int i1 = -1; float v1 = -3.0e38f;
#pragma unroll
        for (int e = 0; e < NE; e++)
            if (e != i0 && acc[e] > v1) { v1 = acc[e]; i1 = e; }
        float t  = expf(v1 - v0);
        float w0 = 1.f / (1.f + t);
        float w1 = t / (1.f + t);
        int s0 = atomicAdd(&g_cnt[i0], 1);
        g_tok[i0 * TMAX + s0] = warp; g_wt[i0 * TMAX + s0] = w0;
        int s1 = atomicAdd(&g_cnt[i1], 1);
        g_tok[i1 * TMAX + s1] = warp; g_wt[i1 * TMAX + s1] = w1;
    }
}

// x -> fp16, elementwise
__global__ void conv_x_kernel(const float4* __restrict__ s, uint2* __restrict__ d, int n4) {
    int i = blockIdx.x * blockDim.x + threadIdx.x;
    int stride = gridDim.x * blockDim.x;
    for (; i < n4; i += stride) {
        float4 v = s[i];
        uint2 o;
        o.x = pack_h2(v.x, v.y);
        o.y = pack_h2(v.z, v.w);
        d[i] = o;
    }
}

// merged transpose + fp16 for all 3 weights, half2-vectorized stores:
// w1,w3: [NE][DD][FF] -> [NE][FF][DD];  w2: [NE][FF][DD] -> [NE][DD][FF]
#define TILES_W1 ((FF / 32) * (DD / 32) * NE)   // 32768
__global__ void trans_all_kernel(const float* __restrict__ w1, __half* __restrict__ d1,
                                 const float* __restrict__ w3, __half* __restrict__ d3,
                                 const float* __restrict__ w2, __half* __restrict__ d2) {
    __shared__ float t[32][33];
    int bid = blockIdx.x;
    const float* src; __half* dst; int R, C;
    if (bid < TILES_W1)          { src = w1; dst = d1; R = DD; C = FF; }
    else if (bid < 2 * TILES_W1) { src = w3; dst = d3; R = DD; C = FF; bid -= TILES_W1; }
    else                         { src = w2; dst = d2; R = FF; C = DD; bid -= 2 * TILES_W1; }
    int tilesC = C / 32, tilesR = R / 32;
    int b   = bid / (tilesC * tilesR);
    int rem = bid % (tilesC * tilesR);
    int c0 = (rem % tilesC) * 32, r0 = (rem / tilesC) * 32;
    const float* s = src + (size_t)b * R * C;
    __half* d = dst + (size_t)b * R * C;
    int lane = threadIdx.x & 31, w = threadIdx.x >> 5;
#pragma unroll
    for (int i = 0; i < 32; i += 8)
        t[w + i][lane] = s[(size_t)(r0 + w + i) * C + c0 + lane];
    __syncthreads();
    // store phase: each lane packs 2 r-adjacent values -> one 4B store
    int m  = lane & 15;           // r-pair index
    int hs = lane >> 4;           // row select within pair of output rows
#pragma unroll
    for (int ci = 0; ci < 2; ci++) {
        int cl = w * 4 + ci * 2 + hs;            // source column = output row
        uint32_t v = pack_h2(t[2 * m][cl], t[2 * m + 1][cl]);
        *(uint32_t*)(d + (size_t)(c0 + cl) * R + r0 + 2 * m) = v;
    }
}

// ======================= GEMM1: H = silu(X W1) * (X W3) * wgt =======================
// fp16, BK=64, block 128x64, 8 warps (4m x 2n), warp tile 32x32 dual.
// A smem [128][72] halves (18432B); B1/B3 [64][72] halves (9216B each).
// Stage 36864B, 2 stages = 72KB -> 2 CTAs/SM.
// Fragment feed via ldmatrix.x4: 24 LDSM per warp-ktile (was 96 LDS.32).
#define G_STAGE_B 36864
#define G_SMEM   (2 * G_STAGE_B)

__global__ void __launch_bounds__(256, 2)
gemm1_mma(const __half* __restrict__ Xh,
          const __half* __restrict__ w1t,
          const __half* __restrict__ w3t) {
    const int e    = blockIdx.z;
    const int cnt  = g_cnt[e];
    const int row0 = blockIdx.x * 128;   // m fast
    if (row0 >= cnt) return;
    const int n0   = blockIdx.y * 64;

    extern __shared__ char smc[];
    const uint32_t sbase = smem_u32(smc);

    const int tid  = threadIdx.x;
    const int lane = tid & 31;
    const int wm   = (tid >> 5) & 3;
    const int wn   = (tid >> 5) >> 2;
    const int gId  = lane >> 2;
    const int tId  = lane & 3;
    const int q    = lane >> 3;          // ldmatrix sub-matrix index
    const int jr   = lane & 7;           // ldmatrix row within sub-matrix

    // ---- ldmatrix per-lane base addresses (byte offsets from stage base) ----
    // A x4 tiles: {rows0-7 k0-7, rows8-15 k0-7, rows0-7 k8-15, rows8-15 k8-15}
    uint32_t aLd[2];
#pragma unroll
    for (int mi = 0; mi < 2; mi++)
        aLd[mi] = sbase + (uint32_t)((wm * 32 + mi * 16 + (q & 1) * 8 + jr) * 144)
                        + (uint32_t)((q >> 1) * 16);
    // B x4 tiles: {ni_a k0-7, ni_a k8-15, ni_b k0-7, ni_b k8-15}
    uint32_t b1Ld[2], b3Ld[2];
#pragma unroll
    for (int p = 0; p < 2; p++) {
        uint32_t nrow = (uint32_t)(wn * 32 + (p * 2 + (q >> 1)) * 8 + jr);
        b1Ld[p] = sbase + 18432u + nrow * 144u + (uint32_t)((q & 1) * 16);
        b3Ld[p] = b1Ld[p] + 9216u;
    }

    // ---- cp.async source/dst precompute ----
    const __half* asrc[4]; uint32_t adst[4];
#pragma unroll
    for (int j = 0; j < 4; j++) {
        int c = tid + 256 * j;
        int row = c >> 3, kc = c & 7;
        int rr = row0 + row; if (rr >= cnt) rr = cnt - 1;
        int tok = g_tok[e * TMAX + rr];
        asrc[j] = Xh + (size_t)tok * DD + kc * 8;
        adst[j] = 144u * row + 16u * kc;
    }
    const __half* bsrc[4]; uint32_t bdst[4];
#pragma unroll
    for (int j = 0; j < 4; j++) {
        int c = tid + 256 * j;
        int mat = c >> 9, cc = c & 511;
        int n = cc >> 3, kc = cc & 7;
        const __half* w = mat ? w3t : w1t;
        bsrc[j] = w + (size_t)e * DD * FF + (size_t)(n0 + n) * DD + kc * 8;
        bdst[j] = 18432u + (uint32_t)mat * 9216u + 144u * n + 16u * kc;
    }

#define G1_ISSUE(KT, S) do {                                        \
        uint32_t so_ = sbase + (uint32_t)(S) * G_STAGE_B;           \
        int k0_ = (KT) * 64;                                        \
        _Pragma("unroll")                                           \
        for (int j = 0; j < 4; j++) cp16(so_ + adst[j], asrc[j] + k0_); \
        _Pragma("unroll")                                           \
        for (int j = 0; j < 4; j++) cp16(so_ + bdst[j], bsrc[j] + k0_); \
    } while (0)

    G1_ISSUE(0, 0); cp_commit();
    G1_ISSUE(1, 1); cp_commit();

    float acc1[2][4][4], acc3[2][4][4];
#pragma unroll
    for (int mi = 0; mi < 2; mi++)
#pragma unroll
        for (int ni = 0; ni < 4; ni++)
#pragma unroll
            for (int qq = 0; qq < 4; qq++) { acc1[mi][ni][qq] = 0.f; acc3[mi][ni][qq] = 0.f; }

    const int NKT = DD / 64;   // 16
    for (int kt = 0; kt < NKT; kt++) {
        cp_wait1();
        __syncthreads();
        const uint32_t stOff = (uint32_t)(kt & 1) * G_STAGE_B;

#pragma unroll
        for (int s = 0; s < 4; s++) {        // 4 x k16 steps
            const uint32_t soff = stOff + (uint32_t)s * 32u;
            uint32_t a[2][4];
            ldsm4(a[0], aLd[0] + soff);
            ldsm4(a[1], aLd[1] + soff);
#pragma unroll
            for (int p = 0; p < 2; p++) {
                uint32_t B1r[4], B3r[4];
                ldsm4(B1r, b1Ld[p] + soff);
                ldsm4(B3r, b3Ld[p] + soff);
#pragma unroll
                for (int qq = 0; qq < 2; qq++) {
                    int ni = 2 * p + qq;
#pragma unroll
                    for (int mi = 0; mi < 2; mi++) {
                        mma16(acc1[mi][ni], a[mi][0], a[mi][1], a[mi][2], a[mi][3],
                              B1r[2 * qq], B1r[2 * qq + 1]);
                        mma16(acc3[mi][ni], a[mi][0], a[mi][1], a[mi][2], a[mi][3],
                              B3r[2 * qq], B3r[2 * qq + 1]);
                    }
                }
            }
        }
        __syncthreads();
        if (kt + 2 < NKT) { G1_ISSUE(kt + 2, kt & 1); }
        cp_commit();
    }

    // ---- epilogue: SwiGLU * gate weight -> g_H (fp16) ----
#pragma unroll
    for (int mi = 0; mi < 2; mi++) {
        int rbase = row0 + wm * 32 + mi * 16 + gId;
#pragma unroll
        for (int half = 0; half < 2; half++) {
            int r = rbase + half * 8;
            if (r < cnt) {
                float wgt = g_wt[e * TMAX + r];
                __half* hp = g_H + ((size_t)e * TMAX + r) * FF;
#pragma unroll
                for (int ni = 0; ni < 4; ni++) {
                    int col = n0 + wn * 32 + ni * 8 + tId * 2;
                    float h1a = acc1[mi][ni][half * 2 + 0];
                    float h1b = acc1[mi][ni][half * 2 + 1];
                    float h3a = acc3[mi][ni][half * 2 + 0];
                    float h3b = acc3[mi][ni][half * 2 + 1];
                    float oa = (h1a / (1.f + __expf(-h1a))) * h3a * wgt;
                    float ob = (h1b / (1.f + __expf(-h1b))) * h3b * wgt;
                    *(uint32_t*)(hp + col) = pack_h2(oa, ob);
                }
            }
        }
    }
}

// ======================= GEMM2: out[tok] += H W2 =======================
// fp16, BK=64, block 128x128, warp tile 32x64, ldmatrix feeds.
__global__ void __launch_bounds__(256, 2)
gemm2_mma(const __half* __restrict__ w2t, float* __restrict__ out) {
    const int e    = blockIdx.z;
    const int cnt  = g_cnt[e];
    const int row0 = blockIdx.x * 128;
    if (row0 >= cnt) return;
    const int n0   = blockIdx.y * 128;

    extern __shared__ char smc[];
    const uint32_t sbase = smem_u32(smc);

    const int tid  = threadIdx.x;
    const int lane = tid & 31;
    const int wm   = (tid >> 5) & 3;
    const int wn   = (tid >> 5) >> 2;
    const int gId  = lane >> 2;
    const int tId  = lane & 3;
    const int q    = lane >> 3;
    const int jr   = lane & 7;

    uint32_t aLd[2];
#pragma unroll
    for (int mi = 0; mi < 2; mi++)
        aLd[mi] = sbase + (uint32_t)((wm * 32 + mi * 16 + (q & 1) * 8 + jr) * 144)
                        + (uint32_t)((q >> 1) * 16);
    uint32_t bLd[4];
#pragma unroll
    for (int p = 0; p < 4; p++) {
        uint32_t nrow = (uint32_t)(wn * 64 + (p * 2 + (q >> 1)) * 8 + jr);
        bLd[p] = sbase + 18432u + nrow * 144u + (uint32_t)((q & 1) * 16);
    }

    const __half* asrc[4]; uint32_t adst[4];
#pragma unroll
    for (int j = 0; j < 4; j++) {
        int c = tid + 256 * j;
        int row = c >> 3, kc = c & 7;
        int rr = row0 + row; if (rr >= cnt) rr = cnt - 1;
        asrc[j] = g_H + ((size_t)e * TMAX + rr) * FF + kc * 8;
        adst[j] = 144u * row + 16u * kc;
    }
    const __half* bsrc[4]; uint32_t bdst[4];
#pragma unroll
    for (int j = 0; j < 4; j++) {
        int c = tid + 256 * j;
        int n = c >> 3, kc = c & 7;
        bsrc[j] = w2t + (size_t)e * FF * DD + (size_t)(n0 + n) * FF + kc * 8;
        bdst[j] = 18432u + 144u * n + 16u * kc;
    }

#define G2_ISSUE(KT, S) do {                                        \
        uint32_t so_ = sbase + (uint32_t)(S) * G_STAGE_B;           \
        int k0_ = (KT) * 64;                                        \
        _Pragma("unroll")                                           \
        for (int j = 0; j < 4; j++) cp16(so_ + adst[j], asrc[j] + k0_); \
        _Pragma("unroll")                                           \
        for (int j = 0; j < 4; j++) cp16(so_ + bdst[j], bsrc[j] + k0_); \
    } while (0)

    G2_ISSUE(0, 0); cp_commit();
    G2_ISSUE(1, 1); cp_commit();

    float acc[2][8][4];
#pragma unroll
    for (int mi = 0; mi < 2; mi++)
#pragma unroll
        for (int ni = 0; ni < 8; ni++)
#pragma unroll
            for (int qq = 0; qq < 4; qq++) acc[mi][ni][qq] = 0.f;

    const int NKT = FF / 64;   // 64
    for (int kt = 0; kt < NKT; kt++) {
        cp_wait1();
        __syncthreads();
        const uint32_t stOff = (uint32_t)(kt & 1) * G_STAGE_B;

#pragma unroll
        for (int s = 0; s < 4; s++) {
            const uint32_t soff = stOff + (uint32_t)s * 32u;
            uint32_t a[2][4];
            ldsm4(a[0], aLd[0] + soff);
            ldsm4(a[1], aLd[1] + soff);
#pragma unroll
            for (int p = 0; p < 4; p++) {
                uint32_t Br[4];
                ldsm4(Br, bLd[p] + soff);
#pragma unroll
                for (int qq = 0; qq < 2; qq++) {
                    int ni = 2 * p + qq;
#pragma unroll
                    for (int mi = 0; mi < 2; mi++)
                        mma16(acc[mi][ni], a[mi][0], a[mi][1], a[mi][2], a[mi][3],
                              Br[2 * qq], Br[2 * qq + 1]);
                }
            }
        }
        __syncthreads();
        if (kt + 2 < NKT) { G2_ISSUE(kt + 2, kt & 1); }
        cp_commit();
    }

    // ---- epilogue: atomic scatter into out (fp32) ----
#pragma unroll
    for (int mi = 0; mi < 2; mi++) {
        int rbase = row0 + wm * 32 + mi * 16 + gId;
#pragma unroll
        for (int half = 0; half < 2; half++) {
            int r = rbase + half * 8;
            if (r < cnt) {
                int tok = g_tok[e * TMAX + r];
                float* op = out + (size_t)tok * DD;
#pragma unroll
                for (int ni = 0; ni < 8; ni++) {
                    int col = n0 + wn * 64 + ni * 8 + tId * 2;
                    atomicAdd(&op[col],     acc[mi][ni][half * 2 + 0]);
                    atomicAdd(&op[col + 1], acc[mi][ni][half * 2 + 1]);
                }
            }
        }
    }
}

// ---------------- host ----------------
extern "C" void kernel_launch(void* const* d_in, const int* in_sizes, int n_in,
                              void* d_out, int out_size) {
    const float* x  = (const float*)d_in[0];
    const float* gw = (const float*)d_in[1];
    const float* w1 = (const float*)d_in[2];
    const float* w2 = (const float*)d_in[3];
    const float* w3 = (const float*)d_in[4];
    float* out = (float*)d_out;
    int T = in_sizes[0] / DD;   // 4096

    void *pXh, *pW1t, *pW2t, *pW3t;
    cudaGetSymbolAddress(&pXh,  g_Xh);
    cudaGetSymbolAddress(&pW1t, g_w1t);
    cudaGetSymbolAddress(&pW2t, g_w2t);
    cudaGetSymbolAddress(&pW3t, g_w3t);

    cudaFuncSetAttribute(gemm1_mma, cudaFuncAttributeMaxDynamicSharedMemorySize, G_SMEM);
    cudaFuncSetAttribute(gemm2_mma, cudaFuncAttributeMaxDynamicSharedMemorySize, G_SMEM);

    // [memset] zero gate conv_x trans_all gemm1 gemm2  (GEMM at profile slot 5)
    cudaMemsetAsync(out, 0, (size_t)out_size * sizeof(float), 0);
    zero_cnt_kernel<<<1, 32>>>();
    gate_kernel<<<(T * 32 + 255) / 256, 256>>>(x, gw, T);

    conv_x_kernel<<<2048, 256>>>((const float4*)x, (uint2*)pXh, T * DD / 4);
    trans_all_kernel<<<3 * TILES_W1, 256>>>(w1, (__half*)pW1t,
                                            w3, (__half*)pW3t,
                                            w2, (__half*)pW2t);

    dim3 g1(TMAX / 128, FF / 64, NE);
    gemm1_mma<<<g1, 256, G_SMEM>>>((const __half*)pXh, (const __half*)pW1t, (const __half*)pW3t);

    dim3 g2(TMAX / 128, DD / 128, NE);
    gemm2_mma<<<g2, 256, G_SMEM>>>((const __half*)pW2t, out);
}